// round 10
// baseline (speedup 1.0000x reference)
#include <cuda_runtime.h>
#include <cstdint>

// out[b,c,l] = y0[b,c,l] * (mean_l x0[b,c,:] + mean_l y0[b,c,:])
// B=64, C=36, L=4096 -> 2304 rows of 4096 fp32.
//
// Persistent CTAs + cp.async double-buffered smem staging: loads for row i+1
// stream into smem while row i is reduced/stored, so the DRAM request pipe
// never drains during the reduce/barrier/store phase (the idle 35% of DRAM
// cycles seen in R1-R9). L2 ecology kept from R8: inputs evict_last(0.75),
// output stores evict_first.

static constexpr int L = 4096;
static constexpr int THREADS = 512;
static constexpr int NWARP = THREADS / 32;
static constexpr int CHUNKS = (L * 4) / (16 * THREADS);   // 2 x 16B per array per thread
static constexpr int STAGE_BYTES = 2 * L * 4;             // x + y = 32 KB
static constexpr int Y_OFF = L * 4;                       // y half of a stage

__device__ __forceinline__ void cpasync16(uint32_t dst, const void* src,
                                          unsigned long long pol) {
    asm volatile("cp.async.cg.shared.global.L2::cache_hint [%0], [%1], 16, %2;"
                 :: "r"(dst), "l"(src), "l"(pol));
}

__device__ __forceinline__ void st_pol(float4* p, float4 v, unsigned long long pol) {
    asm volatile("st.global.L2::cache_hint.v4.f32 [%0], {%1,%2,%3,%4}, %5;"
                 :: "l"(p), "f"(v.x), "f"(v.y), "f"(v.z), "f"(v.w), "l"(pol)
                 : "memory");
}

__global__ __launch_bounds__(THREADS, 2)
void rowmean_scale_cpasync(const float* __restrict__ x,
                           const float* __restrict__ y,
                           float* __restrict__ out, int rows) {
    extern __shared__ char smem[];
    __shared__ float warp_part[NWARP];
    __shared__ float bcast;

    unsigned long long pol_keep, pol_drop;
    asm volatile("createpolicy.fractional.L2::evict_last.b64 %0, 0.75;" : "=l"(pol_keep));
    asm volatile("createpolicy.fractional.L2::evict_first.b64 %0, 1.0;" : "=l"(pol_drop));

    uint32_t sbase;
    asm("{ .reg .u64 t; cvta.to.shared.u64 t, %1; cvt.u32.u64 %0, t; }"
        : "=r"(sbase) : "l"(smem));

    const int tid = threadIdx.x;
    const int warp = tid >> 5;
    const int lane = tid & 31;
    const int grid = gridDim.x;

    // Issue one row's loads into a stage (no commit here).
    auto issue = [&](int stage, int row) {
        if (row < rows) {
            const uint32_t sb = sbase + stage * STAGE_BYTES;
            const float* xr = x + (long long)row * L;
            const float* yr = y + (long long)row * L;
            #pragma unroll
            for (int c = 0; c < CHUNKS; c++) {
                const int e = (tid + c * THREADS) * 4;       // float index
                cpasync16(sb + e * 4,         xr + e, pol_keep);
                cpasync16(sb + Y_OFF + e * 4, yr + e, pol_keep);
            }
        }
    };

    const int r0 = blockIdx.x;
    issue(0, r0);
    asm volatile("cp.async.commit_group;");
    issue(1, r0 + grid);
    asm volatile("cp.async.commit_group;");

    int stage = 0;
    for (int r = r0; r < rows; r += grid) {
        asm volatile("cp.async.wait_group 1;");   // stage for row r is ready
        __syncthreads();

        const float4* xs = reinterpret_cast<const float4*>(smem + stage * STAGE_BYTES);
        const float4* ys = reinterpret_cast<const float4*>(smem + stage * STAGE_BYTES + Y_OFF);

        float s = 0.0f;
        float4 yreg[CHUNKS];
        #pragma unroll
        for (int c = 0; c < CHUNKS; c++) {
            const int idx = tid + c * THREADS;
            float4 xv = xs[idx];
            float4 yv = ys[idx];
            yreg[c] = yv;
            s += (xv.x + xv.y) + (xv.z + xv.w);
            s += (yv.x + yv.y) + (yv.z + yv.w);
        }

        #pragma unroll
        for (int off = 16; off > 0; off >>= 1)
            s += __shfl_xor_sync(0xFFFFFFFFu, s, off);
        if (lane == 0) warp_part[warp] = s;
        __syncthreads();
        if (warp == 0) {
            float v = (lane < NWARP) ? warp_part[lane] : 0.0f;
            #pragma unroll
            for (int off = NWARP / 2; off > 0; off >>= 1)
                v += __shfl_xor_sync(0xFFFFFFFFu, v, off);
            if (lane == 0) bcast = v * (1.0f / (float)L);
        }
        __syncthreads();   // all smem reads for this stage are done before refill
        const float scale = bcast;

        // refill the just-consumed stage with row r + 2*grid (overlaps stores)
        issue(stage, r + 2 * grid);
        asm volatile("cp.async.commit_group;");

        float4* __restrict__ o4 = reinterpret_cast<float4*>(out + (long long)r * L);
        #pragma unroll
        for (int c = 0; c < CHUNKS; c++) {
            const int idx = tid + c * THREADS;
            float4 yv = yreg[c];
            float4 w;
            w.x = yv.x * scale;
            w.y = yv.y * scale;
            w.z = yv.z * scale;
            w.w = yv.w * scale;
            st_pol(&o4[idx], w, pol_drop);
        }

        stage ^= 1;
    }
    asm volatile("cp.async.wait_group 0;");   // drain before CTA exit
}

extern "C" void kernel_launch(void* const* d_in, const int* in_sizes, int n_in,
                              void* d_out, int out_size) {
    const float* x = (const float*)d_in[0];
    const float* y = (const float*)d_in[1];
    float* out = (float*)d_out;
    int rows = out_size / L;  // 2304
    if (rows <= 0) rows = 1;

    const int dyn_smem = 2 * STAGE_BYTES;   // 64 KB
    cudaFuncSetAttribute(rowmean_scale_cpasync,
                         cudaFuncAttributeMaxDynamicSharedMemorySize, dyn_smem);

    int grid = 2 * 148;                     // 2 resident CTAs per SM
    if (grid > rows) grid = rows;
    rowmean_scale_cpasync<<<grid, THREADS, dyn_smem>>>(x, y, out, rows);
}

// round 11
// speedup vs baseline: 1.3898x; 1.3898x over previous
#include <cuda_runtime.h>

// out[b,c,l] = y0[b,c,l] * (mean_l x0[b,c,:] + mean_l y0[b,c,:])
// B=64, C=36, L=4096 -> 2304 rows of 4096 fp32.
//
// R8 base (one CTA per row, wide grid, L2 hints) extended to TWO rows per
// CTA: 8 front-batched LDG.128 per thread (2x outstanding bytes) while the
// reduce/barrier dead phase is shared between the rows -> higher DRAM duty
// cycle per CTA. L2 ecology kept: inputs evict_last(0.75), outputs
// evict_first (R6-R9 evidence).

static constexpr int L = 4096;
static constexpr int THREADS = 512;
static constexpr int V = (L / 4) / THREADS;   // 2 float4 per thread per array per row
static constexpr int NWARP = THREADS / 32;

__device__ __forceinline__ float4 ld_pol(const float4* p, unsigned long long pol) {
    float4 v;
    asm volatile("ld.global.L2::cache_hint.v4.f32 {%0,%1,%2,%3}, [%4], %5;"
                 : "=f"(v.x), "=f"(v.y), "=f"(v.z), "=f"(v.w)
                 : "l"(p), "l"(pol));
    return v;
}

__device__ __forceinline__ void st_pol(float4* p, float4 v, unsigned long long pol) {
    asm volatile("st.global.L2::cache_hint.v4.f32 [%0], {%1,%2,%3,%4}, %5;"
                 :: "l"(p), "f"(v.x), "f"(v.y), "f"(v.z), "f"(v.w), "l"(pol)
                 : "memory");
}

__global__ __launch_bounds__(THREADS, 2)
void rowmean_scale_2row(const float* __restrict__ x,
                        const float* __restrict__ y,
                        float* __restrict__ out) {
    __shared__ float warp_part[2][NWARP];
    __shared__ float bcast[2];

    unsigned long long pol_keep, pol_drop;
    asm volatile("createpolicy.fractional.L2::evict_last.b64 %0, 0.75;" : "=l"(pol_keep));
    asm volatile("createpolicy.fractional.L2::evict_first.b64 %0, 1.0;" : "=l"(pol_drop));

    const long long base0 = (long long)(2 * blockIdx.x) * L;       // row pair
    const float4* __restrict__ x40 = reinterpret_cast<const float4*>(x + base0);
    const float4* __restrict__ y40 = reinterpret_cast<const float4*>(y + base0);
    const float4* __restrict__ x41 = reinterpret_cast<const float4*>(x + base0 + L);
    const float4* __restrict__ y41 = reinterpret_cast<const float4*>(y + base0 + L);

    const int tid = threadIdx.x;
    const int warp = tid >> 5;
    const int lane = tid & 31;

    // Front-batch ALL 8 loads per thread, then reduce.
    float4 xv0[V], yv0[V], xv1[V], yv1[V];
    #pragma unroll
    for (int i = 0; i < V; i++) {
        const int idx = tid + i * THREADS;
        xv0[i] = ld_pol(&x40[idx], pol_keep);
        yv0[i] = ld_pol(&y40[idx], pol_keep);
        xv1[i] = ld_pol(&x41[idx], pol_keep);
        yv1[i] = ld_pol(&y41[idx], pol_keep);
    }

    float s0 = 0.0f, s1 = 0.0f;
    #pragma unroll
    for (int i = 0; i < V; i++) {
        s0 += (xv0[i].x + xv0[i].y) + (xv0[i].z + xv0[i].w);
        s0 += (yv0[i].x + yv0[i].y) + (yv0[i].z + yv0[i].w);
        s1 += (xv1[i].x + xv1[i].y) + (xv1[i].z + xv1[i].w);
        s1 += (yv1[i].x + yv1[i].y) + (yv1[i].z + yv1[i].w);
    }

    #pragma unroll
    for (int off = 16; off > 0; off >>= 1) {
        s0 += __shfl_xor_sync(0xFFFFFFFFu, s0, off);
        s1 += __shfl_xor_sync(0xFFFFFFFFu, s1, off);
    }
    if (lane == 0) { warp_part[0][warp] = s0; warp_part[1][warp] = s1; }
    __syncthreads();
    if (warp == 0) {
        float v0 = (lane < NWARP) ? warp_part[0][lane] : 0.0f;
        float v1 = (lane < NWARP) ? warp_part[1][lane] : 0.0f;
        #pragma unroll
        for (int off = NWARP / 2; off > 0; off >>= 1) {
            v0 += __shfl_xor_sync(0xFFFFFFFFu, v0, off);
            v1 += __shfl_xor_sync(0xFFFFFFFFu, v1, off);
        }
        if (lane == 0) {
            bcast[0] = v0 * (1.0f / (float)L);
            bcast[1] = v1 * (1.0f / (float)L);
        }
    }
    __syncthreads();
    const float sc0 = bcast[0];
    const float sc1 = bcast[1];

    float4* __restrict__ o40 = reinterpret_cast<float4*>(out + base0);
    float4* __restrict__ o41 = reinterpret_cast<float4*>(out + base0 + L);
    #pragma unroll
    for (int i = 0; i < V; i++) {
        const int idx = tid + i * THREADS;
        float4 a = yv0[i], b = yv1[i], r0, r1;
        r0.x = a.x * sc0; r0.y = a.y * sc0; r0.z = a.z * sc0; r0.w = a.w * sc0;
        r1.x = b.x * sc1; r1.y = b.y * sc1; r1.z = b.z * sc1; r1.w = b.w * sc1;
        st_pol(&o40[idx], r0, pol_drop);
        st_pol(&o41[idx], r1, pol_drop);
    }
}

extern "C" void kernel_launch(void* const* d_in, const int* in_sizes, int n_in,
                              void* d_out, int out_size) {
    const float* x = (const float*)d_in[0];
    const float* y = (const float*)d_in[1];
    float* out = (float*)d_out;
    int rows = out_size / L;  // 2304
    if (rows <= 0) rows = 2;
    rowmean_scale_2row<<<rows / 2, THREADS>>>(x, y, out);
}

// round 13
// speedup vs baseline: 1.4354x; 1.0328x over previous
#include <cuda_runtime.h>

// out[b,c,l] = y0[b,c,l] * (mean_l x0[b,c,:] + mean_l y0[b,c,:])
// B=64, C=36, L=4096 -> 2304 rows of 4096 fp32.
//
// R12: small-CTA variant of the winning R8 shape. 256 threads per CTA, one
// row per CTA (V=4 -> 8 front-batched LDG.128/thread). Same resident thread
// count at the 2048/SM cap but 6-8 independent CTAs per SM instead of 4:
// more phase-decorrelated CTAs fill each other's reduce/barrier/store dead
// windows, raising DRAM duty cycle. L2 ecology kept from R8: inputs
// evict_last(0.75), output stores evict_first.

static constexpr int L = 4096;
static constexpr int THREADS = 256;
static constexpr int V = (L / 4) / THREADS;   // 4 float4 per thread per array
static constexpr int NWARP = THREADS / 32;

__device__ __forceinline__ float4 ld_pol(const float4* p, unsigned long long pol) {
    float4 v;
    asm volatile("ld.global.L2::cache_hint.v4.f32 {%0,%1,%2,%3}, [%4], %5;"
                 : "=f"(v.x), "=f"(v.y), "=f"(v.z), "=f"(v.w)
                 : "l"(p), "l"(pol));
    return v;
}

__device__ __forceinline__ void st_pol(float4* p, float4 v, unsigned long long pol) {
    asm volatile("st.global.L2::cache_hint.v4.f32 [%0], {%1,%2,%3,%4}, %5;"
                 :: "l"(p), "f"(v.x), "f"(v.y), "f"(v.z), "f"(v.w), "l"(pol)
                 : "memory");
}

__global__ __launch_bounds__(THREADS)
void rowmean_scale_256(const float* __restrict__ x,
                       const float* __restrict__ y,
                       float* __restrict__ out) {
    __shared__ float warp_part[NWARP];
    __shared__ float bcast;

    unsigned long long pol_keep, pol_drop;
    asm volatile("createpolicy.fractional.L2::evict_last.b64 %0, 0.75;" : "=l"(pol_keep));
    asm volatile("createpolicy.fractional.L2::evict_first.b64 %0, 1.0;" : "=l"(pol_drop));

    const long long base = (long long)blockIdx.x * L;
    const float4* __restrict__ x4 = reinterpret_cast<const float4*>(x + base);
    const float4* __restrict__ y4 = reinterpret_cast<const float4*>(y + base);
    float4* __restrict__ o4 = reinterpret_cast<float4*>(out + base);

    const int tid = threadIdx.x;
    const int warp = tid >> 5;
    const int lane = tid & 31;

    // Front-batch all 8 loads; keep y in registers, fold x on arrival.
    float4 yreg[V];
    float4 xreg[V];
    #pragma unroll
    for (int i = 0; i < V; i++) {
        const int idx = tid + i * THREADS;
        xreg[i] = ld_pol(&x4[idx], pol_keep);
        yreg[i] = ld_pol(&y4[idx], pol_keep);
    }

    float s = 0.0f;
    #pragma unroll
    for (int i = 0; i < V; i++) {
        s += (xreg[i].x + xreg[i].y) + (xreg[i].z + xreg[i].w);
        s += (yreg[i].x + yreg[i].y) + (yreg[i].z + yreg[i].w);
    }

    #pragma unroll
    for (int off = 16; off > 0; off >>= 1)
        s += __shfl_xor_sync(0xFFFFFFFFu, s, off);
    if (lane == 0) warp_part[warp] = s;
    __syncthreads();
    if (warp == 0) {
        float v = (lane < NWARP) ? warp_part[lane] : 0.0f;
        #pragma unroll
        for (int off = NWARP / 2; off > 0; off >>= 1)
            v += __shfl_xor_sync(0xFFFFFFFFu, v, off);
        if (lane == 0) bcast = v * (1.0f / (float)L);
    }
    __syncthreads();
    const float scale = bcast;

    #pragma unroll
    for (int i = 0; i < V; i++) {
        const int idx = tid + i * THREADS;
        float4 yv = yreg[i];
        float4 r;
        r.x = yv.x * scale;
        r.y = yv.y * scale;
        r.z = yv.z * scale;
        r.w = yv.w * scale;
        st_pol(&o4[idx], r, pol_drop);
    }
}

extern "C" void kernel_launch(void* const* d_in, const int* in_sizes, int n_in,
                              void* d_out, int out_size) {
    const float* x = (const float*)d_in[0];
    const float* y = (const float*)d_in[1];
    float* out = (float*)d_out;
    int rows = out_size / L;  // 2304
    if (rows <= 0) rows = 1;
    rowmean_scale_256<<<rows, THREADS>>>(x, y, out);
}